// round 15
// baseline (speedup 1.0000x reference)
#include <cuda_runtime.h>
#include <cuda.h>
#include <cuda_fp16.h>
#include <cstdint>

#define TOKENS 8192
#define IN_F   4096
#define OUT_F  4096

#if defined(__CUDA_ARCH_FEAT_SM103_ALL) || defined(__CUDA_ARCH_FEAT_SM100_ALL) || defined(__CUDA_ARCH_FEAT_SM101_ALL)
#define HAS_TC 1
#else
#define HAS_TC 0
#endif

// ---------------- scratch (device globals: no allocations allowed) ----------
__device__ __half g_xh[(size_t)TOKENS * IN_F];  // Hadamard-transformed x (fp16)
__device__ __half g_w [(size_t)OUT_F  * IN_F];  // dequantized W (fp16)

// ---------------- small PTX helpers ----------------------------------------
__device__ __forceinline__ uint32_t smem_u32(const void* p) {
    uint32_t a;
    asm("{ .reg .u64 t; cvta.to.shared.u64 t, %1; cvt.u32.u64 %0, t; }" : "=r"(a) : "l"(p));
    return a;
}
__device__ __forceinline__ void mbar_init(uint32_t a, uint32_t cnt) {
    asm volatile("mbarrier.init.shared.b64 [%0], %1;" :: "r"(a), "r"(cnt) : "memory");
}
__device__ __forceinline__ void mbar_expect(uint32_t a, uint32_t bytes) {
    asm volatile("mbarrier.arrive.expect_tx.shared.b64 _, [%0], %1;" :: "r"(a), "r"(bytes) : "memory");
}
__device__ __forceinline__ void mbar_wait(uint32_t a, uint32_t parity) {
    asm volatile(
        "{\n\t.reg .pred P;\n\t"
        "WAITLP_%=:\n\t"
        "mbarrier.try_wait.parity.shared::cta.b64 P, [%0], %1, 0x989680;\n\t"
        "@!P bra WAITLP_%=;\n\t"
        "}" :: "r"(a), "r"(parity) : "memory");
}
__device__ __forceinline__ void mbar_arrive_rank0(uint32_t local_addr) {
    asm volatile(
        "{\n\t.reg .b32 rem;\n\t"
        "mapa.shared::cluster.u32 rem, %0, 0;\n\t"
        "mbarrier.arrive.shared::cluster.b64 _, [rem];\n\t"
        "}" :: "r"(local_addr) : "memory");
}
__device__ __forceinline__ void tma2d_cg2(uint32_t dst, const void* map,
                                          int cx, int cy, uint32_t bar) {
    asm volatile(
        "{\n\t.reg .b32 lb;\n\t"
        "and.b32 lb, %4, 0xFEFFFFFF;\n\t"
        "cp.async.bulk.tensor.2d.cta_group::2.shared::cluster.global.tile"
        ".mbarrier::complete_tx::bytes [%0], [%1, {%2, %3}], [lb];\n\t}"
        :: "r"(dst), "l"(map), "r"(cx), "r"(cy), "r"(bar) : "memory");
}
// streaming (evict-first) store: keep out of the way of A/W L2 residency
__device__ __forceinline__ void stg_cs(float* p, float4 o) {
    asm volatile("st.global.cs.v4.f32 [%0], {%1, %2, %3, %4};"
                 :: "l"(p), "f"(o.x), "f"(o.y), "f"(o.z), "f"(o.w) : "memory");
}

// ---------------- kernel 1: fused FWHT(x) + dequant(W) ----------------------
// FWHT now fully vectorized: 2x LDG.128 in layout idx = 8t+q.
//   r8 over q            -> idx bits {0,1,2}
//   shfl.bfly m=1..16    -> idx bits {3,4,5,6,7}   (lane = t&31 = idx bits 3-7)
//   smem radix-4 (warps) -> idx bits {8,9}         (t bits 5-6)
#define NFW ((TOKENS * IN_F) / 1024)                 // 32768
#define NDQ ((OUT_F * (IN_F / 2)) / 512)             // 16384

__device__ __forceinline__ void r8(float v[8]) {
    float a;
    a = v[0]; v[0] = a + v[1]; v[1] = a - v[1];
    a = v[2]; v[2] = a + v[3]; v[3] = a - v[3];
    a = v[4]; v[4] = a + v[5]; v[5] = a - v[5];
    a = v[6]; v[6] = a + v[7]; v[7] = a - v[7];
    a = v[0]; v[0] = a + v[2]; v[2] = a - v[2];
    a = v[1]; v[1] = a + v[3]; v[3] = a - v[3];
    a = v[4]; v[4] = a + v[6]; v[6] = a - v[6];
    a = v[5]; v[5] = a + v[7]; v[7] = a - v[7];
    a = v[0]; v[0] = a + v[4]; v[4] = a - v[4];
    a = v[1]; v[1] = a + v[5]; v[5] = a - v[5];
    a = v[2]; v[2] = a + v[6]; v[6] = a - v[6];
    a = v[3]; v[3] = a + v[7]; v[7] = a - v[7];
}

__global__ void __launch_bounds__(128) prep_kernel(
    const float* __restrict__ x,
    const int* __restrict__ codes,
    const float* __restrict__ grid,
    const float* __restrict__ scales,
    __half* __restrict__ xh,
    __half2* __restrict__ W) {
    int t = threadIdx.x;
    if (blockIdx.x < NFW) {
        __shared__ float s[1024];
        size_t base = (size_t)blockIdx.x * 1024;
        int lane = t & 31;
        float v[8];
        float4 u0 = reinterpret_cast<const float4*>(x + base + 8 * t)[0];
        float4 u1 = reinterpret_cast<const float4*>(x + base + 8 * t)[1];
        v[0] = u0.x; v[1] = u0.y; v[2] = u0.z; v[3] = u0.w;
        v[4] = u1.x; v[5] = u1.y; v[6] = u1.z; v[7] = u1.w;
        r8(v);  // idx bits 0,1,2
#pragma unroll
        for (int m = 1; m <= 16; m <<= 1) {  // idx bits 3..7
#pragma unroll
            for (int q = 0; q < 8; q++) {
                float p = __shfl_xor_sync(0xffffffffu, v[q], m);
                v[q] = (lane & m) ? (p - v[q]) : (v[q] + p);
            }
        }
        // radix-4 butterfly over t bits 5-6 (idx bits 8,9) via one smem pass
        reinterpret_cast<float4*>(s)[2 * t] = make_float4(v[0], v[1], v[2], v[3]);
        reinterpret_cast<float4*>(s)[2 * t + 1] = make_float4(v[4], v[5], v[6], v[7]);
        __syncthreads();
        int tb = t & 31, r = t >> 5;
        float s1 = (r & 1) ? -1.f : 1.f;
        float s2 = (r & 2) ? -1.f : 1.f;
        float s3 = s1 * s2;
        float p0[8], p1[8], p2[8], p3[8];
#pragma unroll
        for (int c = 0; c < 4; c++) {
            float* dst = (c == 0) ? p0 : (c == 1) ? p1 : (c == 2) ? p2 : p3;
            const float4* S = reinterpret_cast<const float4*>(s) + 2 * (tb + 32 * c);
            float4 a0 = S[0], a1 = S[1];
            dst[0] = a0.x; dst[1] = a0.y; dst[2] = a0.z; dst[3] = a0.w;
            dst[4] = a1.x; dst[5] = a1.y; dst[6] = a1.z; dst[7] = a1.w;
        }
#pragma unroll
        for (int q = 0; q < 8; q++)
            v[q] = fmaf(s3, p3[q], fmaf(s2, p2[q], fmaf(s1, p1[q], p0[q])));
        __half2 h[4];
#pragma unroll
        for (int q = 0; q < 4; q++)
            h[q] = __floats2half2_rn(v[2 * q] * 0.03125f, v[2 * q + 1] * 0.03125f);
        *reinterpret_cast<uint4*>(xh + base + 8 * t) = *reinterpret_cast<uint4*>(h);
    } else {
        int g0 = (blockIdx.x - NFW) * 512 + t * 4;
        uint4 c4 = reinterpret_cast<const uint4*>(codes)[g0 >> 2];
        int o  = g0 >> 11;
        int gi = g0 & 2047;
        float sc = __ldg(scales + o * 4 + (gi >> 9));
        __half2 h[4];
        uint32_t cc[4] = {c4.x, c4.y, c4.z, c4.w};
#pragma unroll
        for (int j = 0; j < 4; j++) {
            float2 gv = reinterpret_cast<const float2*>(grid)[cc[j]];
            h[j] = __floats2half2_rn(gv.x * sc, gv.y * sc);
        }
        *reinterpret_cast<uint4*>(W + g0) = *reinterpret_cast<uint4*>(h);
    }
}

// ---------------- kernel 2: persistent cg2 ping-pong GEMM -------------------
// 74 persistent cg2 pairs (148 CTAs). Pair tile = 256x256; contiguous chunks
// (A-tile reuse within chunk). TMEM ping-pong: epilogue of tile lt overlaps
// MMA of lt+1. Epilogue stores are streaming (evict-first).
#define BK 64
#define KIT 64                        // K iters per tile
#define NT 512                        // 32 m-tiles x 16 n-tiles
#define NPAIR 74
#define CHUNK 7
#define STAGES 6
#define A_ST (128 * 128)              // 16 KB (this CTA's 128 M-rows)
#define B_ST (128 * 128)              // 16 KB (this CTA's 128 N-rows)
#define SMA0 1024
#define SMB0 (SMA0 + STAGES * A_ST)
#define SMEM_BYTES (SMB0 + STAGES * B_ST)   // 197632
#define FULLL(s)  (16 + 32 * (s))
#define EMPT(s)   (24 + 32 * (s))
#define MMAD(b)   (224 + 16 * (b))
#define EPID(b)   (256 + 16 * (b))
// idesc cg2 f16: F32 acc (1<<4), f16 a/b, N=256 (32<<17), M=256 (16<<24)
#define IDESC 0x10400010u

__global__ void __launch_bounds__(256, 1) __cluster_dims__(2, 1, 1)
gemm_kernel(
    const __grid_constant__ CUtensorMap tma_a,
    const __grid_constant__ CUtensorMap tma_b,
    const float* __restrict__ bias,
    float* __restrict__ out) {
    extern __shared__ char smem[];
    uint32_t sb = smem_u32(smem);
    int tid = threadIdx.x;
    int wid = tid >> 5, lane = tid & 31;
    int rank = blockIdx.x & 1;
    int pair = blockIdx.x >> 1;                // 0..73
    int t0 = pair * CHUNK;
    int t1 = t0 + CHUNK; if (t1 > NT) t1 = NT;

#if HAS_TC
    if (wid == 0) {
        asm volatile("tcgen05.alloc.cta_group::2.sync.aligned.shared::cta.b32 [%0], %1;"
                     :: "r"(sb), "r"(512u) : "memory");
        asm volatile("tcgen05.relinquish_alloc_permit.cta_group::2.sync.aligned;");
    }
    if (tid == 0) {
        for (int s = 0; s < STAGES; s++) {
            mbar_init(sb + FULLL(s), 1);
            mbar_init(sb + EMPT(s), 1);
        }
        mbar_init(sb + MMAD(0), 1);
        mbar_init(sb + MMAD(1), 1);
        mbar_init(sb + EPID(0), 8);    // 4 warps x 2 CTAs
        mbar_init(sb + EPID(1), 8);
    }
    __syncthreads();
    asm volatile("barrier.cluster.arrive.aligned;" ::: "memory");
    asm volatile("barrier.cluster.wait.aligned;" ::: "memory");

    uint32_t tmem;
    asm volatile("ld.shared.b32 %0, [%1];" : "=r"(tmem) : "r"(sb));

    if (tid == 0) {
        // ---- TMA producer: continuous stage ring across tiles ----
        int s = 0, ph = 1;
        for (int t = t0; t < t1; t++) {
            int m0 = (t >> 4) * 256, n0 = (t & 15) * 256;
            for (int it = 0; it < KIT; ++it) {
                mbar_wait(sb + EMPT(s), (uint32_t)ph);
                if (rank == 0)
                    mbar_expect(sb + FULLL(s), 2 * (A_ST + B_ST));
                tma2d_cg2(sb + SMA0 + s * A_ST, &tma_a, it * BK,
                          m0 + rank * 128, sb + FULLL(s));
                tma2d_cg2(sb + SMB0 + s * B_ST, &tma_b, it * BK,
                          n0 + rank * 128, sb + FULLL(s));
                if (++s == STAGES) { s = 0; ph ^= 1; }
            }
        }
    } else if (tid == 32 && rank == 0) {
        // ---- MMA issuer: ping-pong accumulators ----
        int s = 0, phF = 0;
        int phE0 = 1, phE1 = 1;
        int lt = 0;
        for (int t = t0; t < t1; t++, lt++) {
            int b = lt & 1;
            if (b == 0) { mbar_wait(sb + EPID(0), (uint32_t)phE0); phE0 ^= 1; }
            else        { mbar_wait(sb + EPID(1), (uint32_t)phE1); phE1 ^= 1; }
            uint32_t dcol = tmem + b * 256;
            uint32_t acc = 0;
            for (int it = 0; it < KIT; ++it) {
                mbar_wait(sb + FULLL(s), (uint32_t)phF);
                uint64_t ad = ((uint64_t)2 << 61) | (1ull << 46) | (64ull << 32) | (1ull << 16)
                            | ((uint64_t)((sb + SMA0 + s * A_ST) >> 4) & 0x3FFF);
                uint64_t bd = ((uint64_t)2 << 61) | (1ull << 46) | (64ull << 32) | (1ull << 16)
                            | ((uint64_t)((sb + SMB0 + s * B_ST) >> 4) & 0x3FFF);
#pragma unroll
                for (int kk = 0; kk < 4; kk++) {   // 4 x K=16 f16 chunks
                    asm volatile(
                        "{\n\t.reg .pred p;\n\t"
                        "setp.ne.u32 p, %4, 0;\n\t"
                        "tcgen05.mma.cta_group::2.kind::f16 [%0], %1, %2, %3, "
                        "{%5, %5, %5, %5, %5, %5, %5, %5}, p;\n\t"
                        "}"
                        :: "r"(dcol), "l"(ad + kk * 2), "l"(bd + kk * 2), "r"(IDESC),
                           "r"(acc), "r"(0u) : "memory");
                    acc = 1;
                }
                asm volatile(
                    "tcgen05.commit.cta_group::2.mbarrier::arrive::one.shared::cluster"
                    ".multicast::cluster.b64 [%0], %1;"
                    :: "r"(sb + EMPT(s)), "h"((uint16_t)0x3) : "memory");
                if (++s == STAGES) { s = 0; phF ^= 1; }
            }
            asm volatile(
                "tcgen05.commit.cta_group::2.mbarrier::arrive::one.shared::cluster"
                ".multicast::cluster.b64 [%0], %1;"
                :: "r"(sb + MMAD(b)), "h"((uint16_t)0x3) : "memory");
        }
    } else if (wid >= 4) {
        // ---- epilogue warps 4-7: subpartition sp = wid&3 (rows sp*32..) ----
        int sp = wid & 3;
        int phM0 = 0, phM1 = 0;
        int lt = 0;
        for (int t = t0; t < t1; t++, lt++) {
            int b = lt & 1;
            if (b == 0) { mbar_wait(sb + MMAD(0), (uint32_t)phM0); phM0 ^= 1; }
            else        { mbar_wait(sb + MMAD(1), (uint32_t)phM1); phM1 ^= 1; }
            asm volatile("tcgen05.fence::after_thread_sync;" ::: "memory");
            int m = (t >> 4) * 256 + rank * 128 + sp * 32 + lane;
            int n0 = (t & 15) * 256;
            float* orow = out + (size_t)m * OUT_F + n0;
            const float* brow = bias + n0;
#pragma unroll 1
            for (int j = 0; j < 8; ++j) {
                uint32_t r[32];
                asm volatile("tcgen05.ld.sync.aligned.32x32b.x32.b32 "
                    "{%0, %1, %2, %3, %4, %5, %6, %7, %8, %9, %10, %11, %12, %13, %14, %15, "
                    "%16, %17, %18, %19, %20, %21, %22, %23, %24, %25, %26, %27, %28, %29, %30, %31}, [%32];"
                    : "=r"(r[0]), "=r"(r[1]), "=r"(r[2]), "=r"(r[3]),
                      "=r"(r[4]), "=r"(r[5]), "=r"(r[6]), "=r"(r[7]),
                      "=r"(r[8]), "=r"(r[9]), "=r"(r[10]), "=r"(r[11]),
                      "=r"(r[12]), "=r"(r[13]), "=r"(r[14]), "=r"(r[15]),
                      "=r"(r[16]), "=r"(r[17]), "=r"(r[18]), "=r"(r[19]),
                      "=r"(r[20]), "=r"(r[21]), "=r"(r[22]), "=r"(r[23]),
                      "=r"(r[24]), "=r"(r[25]), "=r"(r[26]), "=r"(r[27]),
                      "=r"(r[28]), "=r"(r[29]), "=r"(r[30]), "=r"(r[31])
                    : "r"(tmem + b * 256 + j * 32));
                asm volatile("tcgen05.wait::ld.sync.aligned;" ::: "memory");
                float f[32];
#pragma unroll
                for (int c = 0; c < 32; c++)
                    f[c] = __uint_as_float(r[c]) + __ldg(brow + j * 32 + c);
#pragma unroll
                for (int q = 0; q < 8; q++) {
                    float4 o;
                    o.x = f[4 * q]; o.y = f[4 * q + 1];
                    o.z = f[4 * q + 2]; o.w = f[4 * q + 3];
                    stg_cs(orow + j * 32 + 4 * q, o);   // evict-first
                }
            }
            if (lane == 0) mbar_arrive_rank0(sb + EPID(b));
        }
    }

    __syncthreads();
    if (wid == 0) {
        asm volatile("tcgen05.dealloc.cta_group::2.sync.aligned.b32 %0, %1;"
                     :: "r"(tmem), "r"(512u));
    }
    asm volatile("barrier.cluster.arrive.aligned;" ::: "memory");
    asm volatile("barrier.cluster.wait.aligned;" ::: "memory");
#else
    // ===== never-run fallback (family-generic PTX pass must compile) =====
    for (int t = t0; t < t1; t++) {
        int m0 = (t >> 4) * 256, n0 = (t & 15) * 256;
        for (int oi = tid; oi < 128 * 256; oi += 256) {
            int r = m0 + rank * 128 + oi / 256;
            int c = n0 + oi % 256;
            float acc = __ldg(bias + c);
            const __half* ar = g_xh + (size_t)r * IN_F;
            const __half* wr = g_w + (size_t)c * IN_F;
            for (int k = 0; k < IN_F; k++)
                acc += __half2float(ar[k]) * __half2float(wr[k]);
            out[(size_t)r * OUT_F + c] = acc;
        }
    }
#endif
}

// ---------------- host launch ------------------------------------------------
extern "C" void kernel_launch(void* const* d_in, const int* in_sizes, int n_in,
                              void* d_out, int out_size) {
    (void)in_sizes; (void)n_in; (void)out_size;
    const float* x      = (const float*)d_in[0];
    const int*   codes  = (const int*)d_in[1];
    const float* grid   = (const float*)d_in[2];
    const float* scales = (const float*)d_in[3];
    const float* bias   = (const float*)d_in[4];
    float* out = (float*)d_out;

    void* xh_ptr = nullptr; void* w_ptr = nullptr;
    cudaGetSymbolAddress(&xh_ptr, g_xh);
    cudaGetSymbolAddress(&w_ptr, g_w);

    typedef CUresult (*EncodeFn)(CUtensorMap*, CUtensorMapDataType, cuuint32_t, void*,
        const cuuint64_t*, const cuuint64_t*, const cuuint32_t*, const cuuint32_t*,
        CUtensorMapInterleave, CUtensorMapSwizzle, CUtensorMapL2promotion,
        CUtensorMapFloatOOBfill);
    void* fp = nullptr;
    cudaDriverEntryPointQueryResult qr;
    cudaGetDriverEntryPoint("cuTensorMapEncodeTiled", &fp, cudaEnableDefault, &qr);
    EncodeFn enc = (EncodeFn)fp;

    CUtensorMap tma_a, tma_b;
    {
        cuuint64_t dims[2]    = {IN_F, TOKENS};
        cuuint64_t strides[1] = {IN_F * 2};    // fp16
        cuuint32_t box[2]     = {BK, 128};     // 64 x 128 (128B rows)
        cuuint32_t es[2]      = {1, 1};
        enc(&tma_a, CU_TENSOR_MAP_DATA_TYPE_FLOAT16, 2, xh_ptr, dims, strides, box, es,
            CU_TENSOR_MAP_INTERLEAVE_NONE, CU_TENSOR_MAP_SWIZZLE_128B,
            CU_TENSOR_MAP_L2_PROMOTION_L2_128B, CU_TENSOR_MAP_FLOAT_OOB_FILL_NONE);
    }
    {
        cuuint64_t dims[2]    = {IN_F, OUT_F};
        cuuint64_t strides[1] = {IN_F * 2};    // fp16
        cuuint32_t box[2]     = {BK, 128};     // 64 x 128
        cuuint32_t es[2]      = {1, 1};
        enc(&tma_b, CU_TENSOR_MAP_DATA_TYPE_FLOAT16, 2, w_ptr, dims, strides, box, es,
            CU_TENSOR_MAP_INTERLEAVE_NONE, CU_TENSOR_MAP_SWIZZLE_128B,
            CU_TENSOR_MAP_L2_PROMOTION_L2_128B, CU_TENSOR_MAP_FLOAT_OOB_FILL_NONE);
    }

    cudaFuncSetAttribute(gemm_kernel, cudaFuncAttributeMaxDynamicSharedMemorySize, SMEM_BYTES);

    prep_kernel<<<NFW + NDQ, 128>>>(x, codes, grid, scales,
                                    (__half*)xh_ptr, (__half2*)w_ptr);
    gemm_kernel<<<dim3(2 * NPAIR, 1), 256, SMEM_BYTES>>>(tma_a, tma_b, bias, out);
}

// round 16
// speedup vs baseline: 1.1200x; 1.1200x over previous
#include <cuda_runtime.h>
#include <cuda.h>
#include <cuda_fp16.h>
#include <cstdint>

#define TOKENS 8192
#define IN_F   4096
#define OUT_F  4096

#if defined(__CUDA_ARCH_FEAT_SM103_ALL) || defined(__CUDA_ARCH_FEAT_SM100_ALL) || defined(__CUDA_ARCH_FEAT_SM101_ALL)
#define HAS_TC 1
#else
#define HAS_TC 0
#endif

// ---------------- scratch (device globals: no allocations allowed) ----------
__device__ __half g_xh[(size_t)TOKENS * IN_F];  // Hadamard-transformed x (fp16)
__device__ __half g_w [(size_t)OUT_F  * IN_F];  // dequantized W (fp16)

// ---------------- small PTX helpers ----------------------------------------
__device__ __forceinline__ uint32_t smem_u32(const void* p) {
    uint32_t a;
    asm("{ .reg .u64 t; cvta.to.shared.u64 t, %1; cvt.u32.u64 %0, t; }" : "=r"(a) : "l"(p));
    return a;
}
__device__ __forceinline__ void mbar_init(uint32_t a, uint32_t cnt) {
    asm volatile("mbarrier.init.shared.b64 [%0], %1;" :: "r"(a), "r"(cnt) : "memory");
}
__device__ __forceinline__ void mbar_expect(uint32_t a, uint32_t bytes) {
    asm volatile("mbarrier.arrive.expect_tx.shared.b64 _, [%0], %1;" :: "r"(a), "r"(bytes) : "memory");
}
__device__ __forceinline__ void mbar_wait(uint32_t a, uint32_t parity) {
    asm volatile(
        "{\n\t.reg .pred P;\n\t"
        "WAITLP_%=:\n\t"
        "mbarrier.try_wait.parity.shared::cta.b64 P, [%0], %1, 0x989680;\n\t"
        "@!P bra WAITLP_%=;\n\t"
        "}" :: "r"(a), "r"(parity) : "memory");
}
// arrive on the same-offset mbarrier in cluster CTA rank 0
__device__ __forceinline__ void mbar_arrive_rank0(uint32_t local_addr) {
    asm volatile(
        "{\n\t.reg .b32 rem;\n\t"
        "mapa.shared::cluster.u32 rem, %0, 0;\n\t"
        "mbarrier.arrive.shared::cluster.b64 _, [rem];\n\t"
        "}" :: "r"(local_addr) : "memory");
}
// cg2 TMA: complete_tx -> rank 0's barrier (bit 24 cleared)
__device__ __forceinline__ void tma2d_cg2(uint32_t dst, const void* map,
                                          int cx, int cy, uint32_t bar) {
    asm volatile(
        "{\n\t.reg .b32 lb;\n\t"
        "and.b32 lb, %4, 0xFEFFFFFF;\n\t"
        "cp.async.bulk.tensor.2d.cta_group::2.shared::cluster.global.tile"
        ".mbarrier::complete_tx::bytes [%0], [%1, {%2, %3}], [lb];\n\t}"
        :: "r"(dst), "l"(map), "r"(cx), "r"(cy), "r"(bar) : "memory");
}

// ---------------- kernel 1: fused FWHT(x) + dequant(W) (round-14 version) ---
#define NFW ((TOKENS * IN_F) / 1024)                 // 32768
#define NDQ ((OUT_F * (IN_F / 2)) / 512)             // 16384

__device__ __forceinline__ void r8(float v[8]) {
    float a;
    a = v[0]; v[0] = a + v[1]; v[1] = a - v[1];
    a = v[2]; v[2] = a + v[3]; v[3] = a - v[3];
    a = v[4]; v[4] = a + v[5]; v[5] = a - v[5];
    a = v[6]; v[6] = a + v[7]; v[7] = a - v[7];
    a = v[0]; v[0] = a + v[2]; v[2] = a - v[2];
    a = v[1]; v[1] = a + v[3]; v[3] = a - v[3];
    a = v[4]; v[4] = a + v[6]; v[6] = a - v[6];
    a = v[5]; v[5] = a + v[7]; v[7] = a - v[7];
    a = v[0]; v[0] = a + v[4]; v[4] = a - v[4];
    a = v[1]; v[1] = a + v[5]; v[5] = a - v[5];
    a = v[2]; v[2] = a + v[6]; v[6] = a - v[6];
    a = v[3]; v[3] = a + v[7]; v[7] = a - v[7];
}

__global__ void __launch_bounds__(128) prep_kernel(
    const float* __restrict__ x,
    const int* __restrict__ codes,
    const float* __restrict__ grid,
    const float* __restrict__ scales,
    __half* __restrict__ xh,
    __half2* __restrict__ W) {
    int t = threadIdx.x;
    if (blockIdx.x < NFW) {
        // FWHT bit coverage: phase1 r8 -> {7,8,9}; phase2 r8 -> {0,1,2};
        // shfl.bfly m=1,2,4,8 -> {3,4,5,6}
        __shared__ float s[1024];
        size_t base = (size_t)blockIdx.x * 1024;
        int lane = t & 31;
        float v[8];
#pragma unroll
        for (int j = 0; j < 8; j++) v[j] = x[base + t + 128 * j];
        r8(v);
#pragma unroll
        for (int j = 0; j < 8; j++) s[t + 128 * j] = v[j];
        __syncthreads();
        float4 p0 = reinterpret_cast<const float4*>(s)[2 * t];
        float4 p1 = reinterpret_cast<const float4*>(s)[2 * t + 1];
        v[0] = p0.x; v[1] = p0.y; v[2] = p0.z; v[3] = p0.w;
        v[4] = p1.x; v[5] = p1.y; v[6] = p1.z; v[7] = p1.w;
        r8(v);
#pragma unroll
        for (int m = 1; m <= 8; m <<= 1) {
#pragma unroll
            for (int q = 0; q < 8; q++) {
                float p = __shfl_xor_sync(0xffffffffu, v[q], m);
                v[q] = (lane & m) ? (p - v[q]) : (v[q] + p);
            }
        }
        __half2 h[4];
#pragma unroll
        for (int q = 0; q < 4; q++)
            h[q] = __floats2half2_rn(v[2 * q] * 0.03125f, v[2 * q + 1] * 0.03125f);
        *reinterpret_cast<uint4*>(xh + base + 8 * t) = *reinterpret_cast<uint4*>(h);
    } else {
        int g0 = (blockIdx.x - NFW) * 512 + t * 4;
        uint4 c4 = reinterpret_cast<const uint4*>(codes)[g0 >> 2];
        int o  = g0 >> 11;
        int gi = g0 & 2047;
        float sc = __ldg(scales + o * 4 + (gi >> 9));
        __half2 h[4];
        uint32_t cc[4] = {c4.x, c4.y, c4.z, c4.w};
#pragma unroll
        for (int j = 0; j < 4; j++) {
            float2 gv = reinterpret_cast<const float2*>(grid)[cc[j]];
            h[j] = __floats2half2_rn(gv.x * sc, gv.y * sc);
        }
        *reinterpret_cast<uint4*>(W + g0) = *reinterpret_cast<uint4*>(h);
    }
}

// ---------------- kernel 2: persistent cg2 ping-pong GEMM -------------------
// 74 persistent cg2 pairs (148 CTAs, 1/SM). Pair tile = M=256 x N=256; tiles
// t: m_idx = t>>4, n_idx = t&15 (consecutive tiles share the A tile). Each
// pair owns a contiguous chunk of <=7 tiles. Accumulators ping-pong between
// TMEM cols [0,256) and [256,512): epilogue of tile lt overlaps MMA of lt+1.
// STAGES=7 (224 KB smem): extra buffering against L2-latency jitter.
#define BK 64
#define KIT 64                        // K iters per tile
#define NT 512                        // 32 m-tiles x 16 n-tiles
#define NPAIR 74
#define CHUNK 7                       // ceil(512/74)
#define STAGES 7
#define A_ST (128 * 128)              // 16 KB (this CTA's 128 M-rows)
#define B_ST (128 * 128)              // 16 KB (this CTA's 128 N-rows)
#define SMA0 1024
#define SMB0 (SMA0 + STAGES * A_ST)
#define SMEM_BYTES (SMB0 + STAGES * B_ST)   // 230400 (<= 232448 max)
#define FULLL(s)  (16 + 32 * (s))     // leader full (tx) barrier
#define EMPT(s)   (24 + 32 * (s))     // empty (multicast commit)
#define MMAD(b)   (256 + 16 * (b))    // mma-done per buffer
#define EPID(b)   (288 + 16 * (b))    // epilogue-done per buffer (on rank 0)
// idesc cg2 f16: F32 acc (1<<4), f16 a/b, N=256 (32<<17), M=256 (16<<24)
#define IDESC 0x10400010u

__global__ void __launch_bounds__(256, 1) __cluster_dims__(2, 1, 1)
gemm_kernel(
    const __grid_constant__ CUtensorMap tma_a,
    const __grid_constant__ CUtensorMap tma_b,
    const float* __restrict__ bias,
    float* __restrict__ out) {
    extern __shared__ char smem[];
    uint32_t sb = smem_u32(smem);
    int tid = threadIdx.x;
    int wid = tid >> 5, lane = tid & 31;
    int rank = blockIdx.x & 1;
    int pair = blockIdx.x >> 1;                // 0..73
    int t0 = pair * CHUNK;
    int t1 = t0 + CHUNK; if (t1 > NT) t1 = NT;

#if HAS_TC
    if (wid == 0) {
        asm volatile("tcgen05.alloc.cta_group::2.sync.aligned.shared::cta.b32 [%0], %1;"
                     :: "r"(sb), "r"(512u) : "memory");
        asm volatile("tcgen05.relinquish_alloc_permit.cta_group::2.sync.aligned;");
    }
    if (tid == 0) {
        for (int s = 0; s < STAGES; s++) {
            mbar_init(sb + FULLL(s), 1);
            mbar_init(sb + EMPT(s), 1);
        }
        mbar_init(sb + MMAD(0), 1);
        mbar_init(sb + MMAD(1), 1);
        mbar_init(sb + EPID(0), 8);    // 4 warps x 2 CTAs
        mbar_init(sb + EPID(1), 8);
    }
    __syncthreads();
    asm volatile("barrier.cluster.arrive.aligned;" ::: "memory");
    asm volatile("barrier.cluster.wait.aligned;" ::: "memory");

    uint32_t tmem;
    asm volatile("ld.shared.b32 %0, [%1];" : "=r"(tmem) : "r"(sb));

    if (tid == 0) {
        // ---- TMA producer: continuous stage ring across tiles ----
        int s = 0, ph = 1;
        for (int t = t0; t < t1; t++) {
            int m0 = (t >> 4) * 256, n0 = (t & 15) * 256;
            for (int it = 0; it < KIT; ++it) {
                mbar_wait(sb + EMPT(s), (uint32_t)ph);
                if (rank == 0)
                    mbar_expect(sb + FULLL(s), 2 * (A_ST + B_ST));
                tma2d_cg2(sb + SMA0 + s * A_ST, &tma_a, it * BK,
                          m0 + rank * 128, sb + FULLL(s));
                tma2d_cg2(sb + SMB0 + s * B_ST, &tma_b, it * BK,
                          n0 + rank * 128, sb + FULLL(s));
                if (++s == STAGES) { s = 0; ph ^= 1; }
            }
        }
    } else if (tid == 32 && rank == 0) {
        // ---- MMA issuer: ping-pong accumulators ----
        int s = 0, phF = 0;
        int phE0 = 1, phE1 = 1;        // first wait on each buffer passes
        int lt = 0;
        for (int t = t0; t < t1; t++, lt++) {
            int b = lt & 1;
            if (b == 0) { mbar_wait(sb + EPID(0), (uint32_t)phE0); phE0 ^= 1; }
            else        { mbar_wait(sb + EPID(1), (uint32_t)phE1); phE1 ^= 1; }
            uint32_t dcol = tmem + b * 256;
            uint32_t acc = 0;
            for (int it = 0; it < KIT; ++it) {
                mbar_wait(sb + FULLL(s), (uint32_t)phF);
                uint64_t ad = ((uint64_t)2 << 61) | (1ull << 46) | (64ull << 32) | (1ull << 16)
                            | ((uint64_t)((sb + SMA0 + s * A_ST) >> 4) & 0x3FFF);
                uint64_t bd = ((uint64_t)2 << 61) | (1ull << 46) | (64ull << 32) | (1ull << 16)
                            | ((uint64_t)((sb + SMB0 + s * B_ST) >> 4) & 0x3FFF);
#pragma unroll
                for (int kk = 0; kk < 4; kk++) {   // 4 x K=16 f16 chunks
                    asm volatile(
                        "{\n\t.reg .pred p;\n\t"
                        "setp.ne.u32 p, %4, 0;\n\t"
                        "tcgen05.mma.cta_group::2.kind::f16 [%0], %1, %2, %3, "
                        "{%5, %5, %5, %5, %5, %5, %5, %5}, p;\n\t"
                        "}"
                        :: "r"(dcol), "l"(ad + kk * 2), "l"(bd + kk * 2), "r"(IDESC),
                           "r"(acc), "r"(0u) : "memory");
                    acc = 1;
                }
                asm volatile(
                    "tcgen05.commit.cta_group::2.mbarrier::arrive::one.shared::cluster"
                    ".multicast::cluster.b64 [%0], %1;"
                    :: "r"(sb + EMPT(s)), "h"((uint16_t)0x3) : "memory");
                if (++s == STAGES) { s = 0; phF ^= 1; }
            }
            asm volatile(
                "tcgen05.commit.cta_group::2.mbarrier::arrive::one.shared::cluster"
                ".multicast::cluster.b64 [%0], %1;"
                :: "r"(sb + MMAD(b)), "h"((uint16_t)0x3) : "memory");
        }
    } else if (wid >= 4) {
        // ---- epilogue warps 4-7: subpartition sp = wid&3 (rows sp*32..) ----
        int sp = wid & 3;
        int phM0 = 0, phM1 = 0;
        int lt = 0;
        for (int t = t0; t < t1; t++, lt++) {
            int b = lt & 1;
            if (b == 0) { mbar_wait(sb + MMAD(0), (uint32_t)phM0); phM0 ^= 1; }
            else        { mbar_wait(sb + MMAD(1), (uint32_t)phM1); phM1 ^= 1; }
            asm volatile("tcgen05.fence::after_thread_sync;" ::: "memory");
            int m = (t >> 4) * 256 + rank * 128 + sp * 32 + lane;
            int n0 = (t & 15) * 256;
            float* orow = out + (size_t)m * OUT_F + n0;
            const float* brow = bias + n0;
#pragma unroll 1
            for (int j = 0; j < 8; ++j) {
                uint32_t r[32];
                asm volatile("tcgen05.ld.sync.aligned.32x32b.x32.b32 "
                    "{%0, %1, %2, %3, %4, %5, %6, %7, %8, %9, %10, %11, %12, %13, %14, %15, "
                    "%16, %17, %18, %19, %20, %21, %22, %23, %24, %25, %26, %27, %28, %29, %30, %31}, [%32];"
                    : "=r"(r[0]), "=r"(r[1]), "=r"(r[2]), "=r"(r[3]),
                      "=r"(r[4]), "=r"(r[5]), "=r"(r[6]), "=r"(r[7]),
                      "=r"(r[8]), "=r"(r[9]), "=r"(r[10]), "=r"(r[11]),
                      "=r"(r[12]), "=r"(r[13]), "=r"(r[14]), "=r"(r[15]),
                      "=r"(r[16]), "=r"(r[17]), "=r"(r[18]), "=r"(r[19]),
                      "=r"(r[20]), "=r"(r[21]), "=r"(r[22]), "=r"(r[23]),
                      "=r"(r[24]), "=r"(r[25]), "=r"(r[26]), "=r"(r[27]),
                      "=r"(r[28]), "=r"(r[29]), "=r"(r[30]), "=r"(r[31])
                    : "r"(tmem + b * 256 + j * 32));
                asm volatile("tcgen05.wait::ld.sync.aligned;" ::: "memory");
                float f[32];
#pragma unroll
                for (int c = 0; c < 32; c++)
                    f[c] = __uint_as_float(r[c]) + __ldg(brow + j * 32 + c);
#pragma unroll
                for (int q = 0; q < 8; q++) {
                    float4 o;
                    o.x = f[4 * q]; o.y = f[4 * q + 1];
                    o.z = f[4 * q + 2]; o.w = f[4 * q + 3];
                    reinterpret_cast<float4*>(orow + j * 32)[q] = o;
                }
            }
            if (lane == 0) mbar_arrive_rank0(sb + EPID(b));
        }
    }

    __syncthreads();
    if (wid == 0) {
        asm volatile("tcgen05.dealloc.cta_group::2.sync.aligned.b32 %0, %1;"
                     :: "r"(tmem), "r"(512u));
    }
    asm volatile("barrier.cluster.arrive.aligned;" ::: "memory");
    asm volatile("barrier.cluster.wait.aligned;" ::: "memory");
#else
    // ===== never-run fallback (family-generic PTX pass must compile) =====
    for (int t = t0; t < t1; t++) {
        int m0 = (t >> 4) * 256, n0 = (t & 15) * 256;
        for (int oi = tid; oi < 128 * 256; oi += 256) {
            int r = m0 + rank * 128 + oi / 256;
            int c = n0 + oi % 256;
            float acc = __ldg(bias + c);
            const __half* ar = g_xh + (size_t)r * IN_F;
            const __half* wr = g_w + (size_t)c * IN_F;
            for (int k = 0; k < IN_F; k++)
                acc += __half2float(ar[k]) * __half2float(wr[k]);
            out[(size_t)r * OUT_F + c] = acc;
        }
    }
#endif
}

// ---------------- host launch ------------------------------------------------
extern "C" void kernel_launch(void* const* d_in, const int* in_sizes, int n_in,
                              void* d_out, int out_size) {
    (void)in_sizes; (void)n_in; (void)out_size;
    const float* x      = (const float*)d_in[0];
    const int*   codes  = (const int*)d_in[1];
    const float* grid   = (const float*)d_in[2];
    const float* scales = (const float*)d_in[3];
    const float* bias   = (const float*)d_in[4];
    float* out = (float*)d_out;

    void* xh_ptr = nullptr; void* w_ptr = nullptr;
    cudaGetSymbolAddress(&xh_ptr, g_xh);
    cudaGetSymbolAddress(&w_ptr, g_w);

    typedef CUresult (*EncodeFn)(CUtensorMap*, CUtensorMapDataType, cuuint32_t, void*,
        const cuuint64_t*, const cuuint64_t*, const cuuint32_t*, const cuuint32_t*,
        CUtensorMapInterleave, CUtensorMapSwizzle, CUtensorMapL2promotion,
        CUtensorMapFloatOOBfill);
    void* fp = nullptr;
    cudaDriverEntryPointQueryResult qr;
    cudaGetDriverEntryPoint("cuTensorMapEncodeTiled", &fp, cudaEnableDefault, &qr);
    EncodeFn enc = (EncodeFn)fp;

    CUtensorMap tma_a, tma_b;
    {
        cuuint64_t dims[2]    = {IN_F, TOKENS};
        cuuint64_t strides[1] = {IN_F * 2};    // fp16
        cuuint32_t box[2]     = {BK, 128};     // 64 x 128 (128B rows)
        cuuint32_t es[2]      = {1, 1};
        enc(&tma_a, CU_TENSOR_MAP_DATA_TYPE_FLOAT16, 2, xh_ptr, dims, strides, box, es,
            CU_TENSOR_MAP_INTERLEAVE_NONE, CU_TENSOR_MAP_SWIZZLE_128B,
            CU_TENSOR_MAP_L2_PROMOTION_L2_128B, CU_TENSOR_MAP_FLOAT_OOB_FILL_NONE);
    }
    {
        cuuint64_t dims[2]    = {IN_F, OUT_F};
        cuuint64_t strides[1] = {IN_F * 2};    // fp16
        cuuint32_t box[2]     = {BK, 128};     // 64 x 128
        cuuint32_t es[2]      = {1, 1};
        enc(&tma_b, CU_TENSOR_MAP_DATA_TYPE_FLOAT16, 2, w_ptr, dims, strides, box, es,
            CU_TENSOR_MAP_INTERLEAVE_NONE, CU_TENSOR_MAP_SWIZZLE_128B,
            CU_TENSOR_MAP_L2_PROMOTION_L2_128B, CU_TENSOR_MAP_FLOAT_OOB_FILL_NONE);
    }

    cudaFuncSetAttribute(gemm_kernel, cudaFuncAttributeMaxDynamicSharedMemorySize, SMEM_BYTES);

    prep_kernel<<<NFW + NDQ, 128>>>(x, codes, grid, scales,
                                    (__half*)xh_ptr, (__half2*)w_ptr);
    gemm_kernel<<<dim3(2 * NPAIR, 1), 256, SMEM_BYTES>>>(tma_a, tma_b, bias, out);
}